// round 2
// baseline (speedup 1.0000x reference)
#include <cuda_runtime.h>
#include <math.h>
#include <float.h>

// Swin window attention, fully fused: LN -> QKV -> MHA(8 heads, hd=16) -> out proj.
// One CTA per 7x7 window (4096 CTAs), 256 threads, 2 CTAs/SM.
// GEMM phases use packed fma.rn.f32x2 (SASS FFMA2) for 2x fp32 MAC rate on sm_103a.

#define N_TOK 49     // tokens per window
#define CC    128    // channels
#define C3    384    // 3*C
#define NHH   8      // heads
#define HDD   16     // head dim
#define HDP   17     // padded head-dim stride (odd -> conflict-free)

#define SMEM_FLOATS (N_TOK*CC + 3*NHH*N_TOK*HDP + NHH*64)

typedef unsigned long long u64;

__device__ __forceinline__ u64 pack2(float x, float y) {
    u64 r; asm("mov.b64 %0, {%1, %2};" : "=l"(r) : "f"(x), "f"(y)); return r;
}
__device__ __forceinline__ u64 bcast2(float x) {
    u64 r; asm("mov.b64 %0, {%1, %1};" : "=l"(r) : "f"(x)); return r;
}
__device__ __forceinline__ void unpack2(u64 v, float& x, float& y) {
    asm("mov.b64 {%0, %1}, %2;" : "=f"(x), "=f"(y) : "l"(v));
}
__device__ __forceinline__ void fma2(u64& d, u64 a, u64 b) {
    asm("fma.rn.f32x2 %0, %1, %2, %3;" : "=l"(d) : "l"(a), "l"(b), "l"(d));
}

__global__ void __launch_bounds__(256, 2)
swin_fused_kernel(const float* __restrict__ x,
                  const float* __restrict__ ln_g,
                  const float* __restrict__ ln_b,
                  const float* __restrict__ w_qkv,
                  const float* __restrict__ b_qkv,
                  const float* __restrict__ w_out,
                  const float* __restrict__ b_out,
                  float* __restrict__ out)
{
    extern __shared__ float sm[];
    float* xn   = sm;                         // [49][128]  (xn, later attn output)
    float* qkvs = sm + N_TOK*CC;              // [3][8][49][17]
    float* psm  = qkvs + 3*NHH*N_TOK*HDP;     // [8][64] softmax probs per head

    const int tid  = threadIdx.x;
    const int lane = tid & 31;
    const int wrp  = tid >> 5;

    const int w  = blockIdx.x;
    const int b  = w >> 6;
    const int wi = w & 63;
    const int wr = wi >> 3;
    const int wc = wi & 7;
    const size_t gbase = (size_t)b * (3136 * 128);

    // ---------------- Phase A: gather window + LayerNorm ----------------
    {
        const float4 gv = *(const float4*)(ln_g + 4*lane);
        const float4 bv = *(const float4*)(ln_b + 4*lane);
        for (int t = wrp; t < N_TOK; t += 8) {
            const int ti = t / 7, tj = t - ti*7;
            const int n  = (wr*7 + ti)*56 + (wc*7 + tj);
            const float4 xv = *(const float4*)(x + gbase + (size_t)n*CC + 4*lane);
            float s1 = xv.x + xv.y + xv.z + xv.w;
            float s2 = xv.x*xv.x + xv.y*xv.y + xv.z*xv.z + xv.w*xv.w;
            #pragma unroll
            for (int o = 16; o > 0; o >>= 1) {
                s1 += __shfl_xor_sync(0xffffffffu, s1, o);
                s2 += __shfl_xor_sync(0xffffffffu, s2, o);
            }
            const float mu   = s1 * (1.0f/128.0f);
            const float var  = fmaxf(s2 * (1.0f/128.0f) - mu*mu, 0.0f);
            const float rstd = rsqrtf(var + 1e-5f);
            float4 o4;
            o4.x = (xv.x - mu)*rstd*gv.x + bv.x;
            o4.y = (xv.y - mu)*rstd*gv.y + bv.y;
            o4.z = (xv.z - mu)*rstd*gv.z + bv.z;
            o4.w = (xv.w - mu)*rstd*gv.w + bv.w;
            *(float4*)(xn + t*CC + 4*lane) = o4;
        }
    }
    __syncthreads();

    // Row assignment for the GEMM phases: warp wrp owns rows wrp, wrp+8, ...
    int rr[7];
    #pragma unroll
    for (int i = 0; i < 7; ++i) { int r = wrp + 8*i; rr[i] = (r < N_TOK) ? r : (N_TOK-1); }

    // ---------------- Phase B: QKV GEMM  [49,128]@[128,384]+b  (FFMA2) ----------------
    // Thread computes 7 rows x 4 cols (cols = 4*lane .. 4*lane+3 within a 128-col tile),
    // packed as 2 f32x2 accumulators per row.
    const int hh = lane >> 2;          // head of this thread's 4 columns
    const int dd = (lane & 3) << 2;    // head-dim offset
    #pragma unroll
    for (int jt = 0; jt < 3; ++jt) {   // jt: 0=q, 1=k, 2=v
        const float4 bias = *(const float4*)(b_qkv + jt*CC + 4*lane);
        u64 accA[7], accB[7];
        const u64 bA = pack2(bias.x, bias.y), bB = pack2(bias.z, bias.w);
        #pragma unroll
        for (int i = 0; i < 7; ++i) { accA[i] = bA; accB[i] = bB; }
        const float* wp = w_qkv + jt*CC + 4*lane;
        #pragma unroll 2
        for (int k = 0; k < CC; k += 4) {
            const float4 w0 = *(const float4*)(wp + (size_t)(k+0)*C3);
            const float4 w1 = *(const float4*)(wp + (size_t)(k+1)*C3);
            const float4 w2 = *(const float4*)(wp + (size_t)(k+2)*C3);
            const float4 w3 = *(const float4*)(wp + (size_t)(k+3)*C3);
            const u64 w0a = pack2(w0.x,w0.y), w0b = pack2(w0.z,w0.w);
            const u64 w1a = pack2(w1.x,w1.y), w1b = pack2(w1.z,w1.w);
            const u64 w2a = pack2(w2.x,w2.y), w2b = pack2(w2.z,w2.w);
            const u64 w3a = pack2(w3.x,w3.y), w3b = pack2(w3.z,w3.w);
            #pragma unroll
            for (int i = 0; i < 7; ++i) {
                const float4 a4 = *(const float4*)(xn + rr[i]*CC + k);
                u64 t;
                t = bcast2(a4.x); fma2(accA[i], t, w0a); fma2(accB[i], t, w0b);
                t = bcast2(a4.y); fma2(accA[i], t, w1a); fma2(accB[i], t, w1b);
                t = bcast2(a4.z); fma2(accA[i], t, w2a); fma2(accB[i], t, w2b);
                t = bcast2(a4.w); fma2(accA[i], t, w3a); fma2(accB[i], t, w3b);
            }
        }
        float* qb = qkvs + (size_t)((jt*NHH + hh)*N_TOK)*HDP + dd;
        #pragma unroll
        for (int i = 0; i < 7; ++i) {
            if (wrp + 8*i < N_TOK) {
                float* p = qb + rr[i]*HDP;
                unpack2(accA[i], p[0], p[1]);
                unpack2(accB[i], p[2], p[3]);
            }
        }
    }
    __syncthreads();

    // ---------------- Phase C: attention, one warp per head ----------------
    {
        const int h = wrp;
        const float* qh = qkvs + (size_t)((0*NHH + h)*N_TOK)*HDP;
        const float* kh = qkvs + (size_t)((1*NHH + h)*N_TOK)*HDP;
        const float* vh = qkvs + (size_t)((2*NHH + h)*N_TOK)*HDP;
        float* pp = psm + h*64;
        pp[lane + 32] = 0.0f;          // keys 49..63 stay zero forever
        __syncwarp();

        const int  klo  = lane;                       // key index #1 (always < 49)
        const bool hiv  = (lane + 32) < N_TOK;        // key index #2 valid?
        const int  khi  = hiv ? lane + 32 : (N_TOK-1);
        const int  davd = lane & 15;                  // AV: this lane's head-dim
        const int  half = lane >> 4;                  // AV: even/odd key split

        for (int r = 0; r < N_TOK; ++r) {
            // scores for keys klo, khi
            float s0 = 0.f, s1 = 0.f;
            #pragma unroll
            for (int d = 0; d < HDD; ++d) {
                const float qd = qh[r*HDP + d];
                s0 += qd * kh[klo*HDP + d];
                s1 += qd * kh[khi*HDP + d];
            }
            s0 *= 0.25f;                               // scale = hd^-0.5 = 1/4
            s1 = hiv ? s1*0.25f : -FLT_MAX;
            // softmax over 49 scores (2 per lane)
            float m = fmaxf(s0, s1);
            #pragma unroll
            for (int o = 16; o > 0; o >>= 1)
                m = fmaxf(m, __shfl_xor_sync(0xffffffffu, m, o));
            float p0 = __expf(s0 - m);
            float p1 = hiv ? __expf(s1 - m) : 0.f;
            float s = p0 + p1;
            #pragma unroll
            for (int o = 16; o > 0; o >>= 1)
                s += __shfl_xor_sync(0xffffffffu, s, o);
            const float inv = __fdividef(1.0f, s);
            pp[lane] = p0 * inv;
            if (hiv) pp[lane + 32] = p1 * inv;
            __syncwarp();
            // P @ V: lanes 0..15 do even keys, 16..31 odd keys, combine via shfl
            float a = 0.f;
            #pragma unroll
            for (int kk = 0; kk < 25; ++kk) {
                const int kix = 2*kk + half;                   // up to 49
                const int kc  = (kix < N_TOK) ? kix : (N_TOK-1);
                a += pp[kix] * vh[kc*HDP + davd];              // pp[49]==0
            }
            a += __shfl_xor_sync(0xffffffffu, a, 16);
            if (half == 0) xn[r*CC + h*HDD + davd] = a;        // reuse xn as attn buf
            __syncwarp();
        }
    }
    __syncthreads();

    // ---------------- Phase D: out projection + window merge  (FFMA2) ----------------
    {
        const float4 bias = *(const float4*)(b_out + 4*lane);
        u64 accA[7], accB[7];
        const u64 bA = pack2(bias.x, bias.y), bB = pack2(bias.z, bias.w);
        #pragma unroll
        for (int i = 0; i < 7; ++i) { accA[i] = bA; accB[i] = bB; }
        const float* wp = w_out + 4*lane;
        #pragma unroll 2
        for (int k = 0; k < CC; k += 4) {
            const float4 w0 = *(const float4*)(wp + (size_t)(k+0)*CC);
            const float4 w1 = *(const float4*)(wp + (size_t)(k+1)*CC);
            const float4 w2 = *(const float4*)(wp + (size_t)(k+2)*CC);
            const float4 w3 = *(const float4*)(wp + (size_t)(k+3)*CC);
            const u64 w0a = pack2(w0.x,w0.y), w0b = pack2(w0.z,w0.w);
            const u64 w1a = pack2(w1.x,w1.y), w1b = pack2(w1.z,w1.w);
            const u64 w2a = pack2(w2.x,w2.y), w2b = pack2(w2.z,w2.w);
            const u64 w3a = pack2(w3.x,w3.y), w3b = pack2(w3.z,w3.w);
            #pragma unroll
            for (int i = 0; i < 7; ++i) {
                const float4 a4 = *(const float4*)(xn + rr[i]*CC + k);
                u64 t;
                t = bcast2(a4.x); fma2(accA[i], t, w0a); fma2(accB[i], t, w0b);
                t = bcast2(a4.y); fma2(accA[i], t, w1a); fma2(accB[i], t, w1b);
                t = bcast2(a4.z); fma2(accA[i], t, w2a); fma2(accB[i], t, w2b);
                t = bcast2(a4.w); fma2(accA[i], t, w3a); fma2(accB[i], t, w3b);
            }
        }
        #pragma unroll
        for (int i = 0; i < 7; ++i) {
            const int r = wrp + 8*i;
            if (r < N_TOK) {
                const int ti = r / 7, tj = r - ti*7;
                const int n  = (wr*7 + ti)*56 + (wc*7 + tj);
                float4 o4;
                unpack2(accA[i], o4.x, o4.y);
                unpack2(accB[i], o4.z, o4.w);
                *(float4*)(out + gbase + (size_t)n*CC + 4*lane) = o4;
            }
        }
    }
}

extern "C" void kernel_launch(void* const* d_in, const int* in_sizes, int n_in,
                              void* d_out, int out_size)
{
    const float* x     = (const float*)d_in[0];
    const float* ln_g  = (const float*)d_in[1];
    const float* ln_b  = (const float*)d_in[2];
    const float* w_qkv = (const float*)d_in[3];
    const float* b_qkv = (const float*)d_in[4];
    const float* w_out = (const float*)d_in[5];
    const float* b_out = (const float*)d_in[6];
    float* out = (float*)d_out;

    const int smem_bytes = SMEM_FLOATS * (int)sizeof(float);
    cudaFuncSetAttribute(swin_fused_kernel,
                         cudaFuncAttributeMaxDynamicSharedMemorySize, smem_bytes);
    swin_fused_kernel<<<4096, 256, smem_bytes>>>(x, ln_g, ln_b, w_qkv, b_qkv,
                                                 w_out, b_out, out);
}

// round 5
// speedup vs baseline: 1.2981x; 1.2981x over previous
#include <cuda_runtime.h>
#include <math.h>
#include <float.h>

// Swin window attention, fully fused: LN -> QKV -> MHA(8 heads, hd=16) -> out proj.
// One CTA per 7x7 window (4096 CTAs), 256 threads, 2 CTAs/SM.
// GEMMs use packed fma.rn.f32x2; attention keeps K and V in registers.

#define N_TOK 49     // tokens per window
#define CC    128    // channels
#define C3    384    // 3*C
#define NHH   8      // heads
#define HDD   16     // head dim
#define HDP   18     // padded head-dim stride (even -> 8B-aligned pair loads)

#define SMEM_FLOATS (N_TOK*CC + 3*NHH*N_TOK*HDP + NHH*64)

typedef unsigned long long u64;

__device__ __forceinline__ u64 pack2(float x, float y) {
    u64 r; asm("mov.b64 %0, {%1, %2};" : "=l"(r) : "f"(x), "f"(y)); return r;
}
__device__ __forceinline__ u64 bcast2(float x) {
    u64 r; asm("mov.b64 %0, {%1, %1};" : "=l"(r) : "f"(x)); return r;
}
__device__ __forceinline__ void unpack2(u64 v, float& x, float& y) {
    asm("mov.b64 {%0, %1}, %2;" : "=f"(x), "=f"(y) : "l"(v));
}
__device__ __forceinline__ void fma2(u64& d, u64 a, u64 b) {
    asm("fma.rn.f32x2 %0, %1, %2, %3;" : "=l"(d) : "l"(a), "l"(b), "l"(d));
}
__device__ __forceinline__ u64 add2(u64 a, u64 b) {
    u64 r; asm("add.rn.f32x2 %0, %1, %2;" : "=l"(r) : "l"(a), "l"(b)); return r;
}

__global__ void __launch_bounds__(256, 2)
swin_fused_kernel(const float* __restrict__ x,
                  const float* __restrict__ ln_g,
                  const float* __restrict__ ln_b,
                  const float* __restrict__ w_qkv,
                  const float* __restrict__ b_qkv,
                  const float* __restrict__ w_out,
                  const float* __restrict__ b_out,
                  float* __restrict__ out)
{
    extern __shared__ float sm[];
    float* xn   = sm;                         // [49][128]  (xn, later attn output)
    float* qkvs = sm + N_TOK*CC;              // [3][8][49][18]
    float* psm  = qkvs + 3*NHH*N_TOK*HDP;     // [8][64] softmax probs per head

    const int tid  = threadIdx.x;
    const int lane = tid & 31;
    const int wrp  = tid >> 5;

    const int w  = blockIdx.x;
    const int b  = w >> 6;
    const int wi = w & 63;
    const int wr = wi >> 3;
    const int wc = wi & 7;
    const size_t gbase = (size_t)b * (3136 * 128);

    // ---------------- Phase A: gather window + LayerNorm ----------------
    {
        const float4 gv = *(const float4*)(ln_g + 4*lane);
        const float4 bv = *(const float4*)(ln_b + 4*lane);
        for (int t = wrp; t < N_TOK; t += 8) {
            const int ti = t / 7, tj = t - ti*7;
            const int n  = (wr*7 + ti)*56 + (wc*7 + tj);
            const float4 xv = *(const float4*)(x + gbase + (size_t)n*CC + 4*lane);
            float s1 = xv.x + xv.y + xv.z + xv.w;
            float s2 = xv.x*xv.x + xv.y*xv.y + xv.z*xv.z + xv.w*xv.w;
            #pragma unroll
            for (int o = 16; o > 0; o >>= 1) {
                s1 += __shfl_xor_sync(0xffffffffu, s1, o);
                s2 += __shfl_xor_sync(0xffffffffu, s2, o);
            }
            const float mu   = s1 * (1.0f/128.0f);
            const float var  = fmaxf(s2 * (1.0f/128.0f) - mu*mu, 0.0f);
            const float rstd = rsqrtf(var + 1e-5f);
            float4 o4;
            o4.x = (xv.x - mu)*rstd*gv.x + bv.x;
            o4.y = (xv.y - mu)*rstd*gv.y + bv.y;
            o4.z = (xv.z - mu)*rstd*gv.z + bv.z;
            o4.w = (xv.w - mu)*rstd*gv.w + bv.w;
            *(float4*)(xn + t*CC + 4*lane) = o4;
        }
    }
    __syncthreads();

    // Row assignment for the GEMM phases: warp wrp owns rows wrp, wrp+8, ...
    int rr[7];
    #pragma unroll
    for (int i = 0; i < 7; ++i) { int r = wrp + 8*i; rr[i] = (r < N_TOK) ? r : (N_TOK-1); }

    // ---------------- Phase B: QKV GEMM  [49,128]@[128,384]+b  (FFMA2) ----------------
    const int hh = lane >> 2;          // head of this thread's 4 columns
    const int dd = (lane & 3) << 2;    // head-dim offset
    #pragma unroll
    for (int jt = 0; jt < 3; ++jt) {   // jt: 0=q, 1=k, 2=v
        const float4 bias = *(const float4*)(b_qkv + jt*CC + 4*lane);
        u64 accA[7], accB[7];
        const u64 bA = pack2(bias.x, bias.y), bB = pack2(bias.z, bias.w);
        #pragma unroll
        for (int i = 0; i < 7; ++i) { accA[i] = bA; accB[i] = bB; }
        const float* wp = w_qkv + jt*CC + 4*lane;
        #pragma unroll 2
        for (int k = 0; k < CC; k += 4) {
            const float4 w0 = *(const float4*)(wp + (size_t)(k+0)*C3);
            const float4 w1 = *(const float4*)(wp + (size_t)(k+1)*C3);
            const float4 w2 = *(const float4*)(wp + (size_t)(k+2)*C3);
            const float4 w3 = *(const float4*)(wp + (size_t)(k+3)*C3);
            const u64 w0a = pack2(w0.x,w0.y), w0b = pack2(w0.z,w0.w);
            const u64 w1a = pack2(w1.x,w1.y), w1b = pack2(w1.z,w1.w);
            const u64 w2a = pack2(w2.x,w2.y), w2b = pack2(w2.z,w2.w);
            const u64 w3a = pack2(w3.x,w3.y), w3b = pack2(w3.z,w3.w);
            #pragma unroll
            for (int i = 0; i < 7; ++i) {
                const float4 a4 = *(const float4*)(xn + rr[i]*CC + k);
                u64 t;
                t = bcast2(a4.x); fma2(accA[i], t, w0a); fma2(accB[i], t, w0b);
                t = bcast2(a4.y); fma2(accA[i], t, w1a); fma2(accB[i], t, w1b);
                t = bcast2(a4.z); fma2(accA[i], t, w2a); fma2(accB[i], t, w2b);
                t = bcast2(a4.w); fma2(accA[i], t, w3a); fma2(accB[i], t, w3b);
            }
        }
        float* qb = qkvs + (size_t)((jt*NHH + hh)*N_TOK)*HDP + dd;
        #pragma unroll
        for (int i = 0; i < 7; ++i) {
            if (wrp + 8*i < N_TOK) {
                float* p = qb + rr[i]*HDP;
                unpack2(accA[i], p[0], p[1]);
                unpack2(accB[i], p[2], p[3]);
            }
        }
    }
    __syncthreads();

    // ---------------- Phase C: attention, one warp per head, K/V in registers ----------------
    {
        const int h = wrp;
        const float* qh = qkvs + (size_t)((0*NHH + h)*N_TOK)*HDP;
        const float* kh = qkvs + (size_t)((1*NHH + h)*N_TOK)*HDP;
        const float* vh = qkvs + (size_t)((2*NHH + h)*N_TOK)*HDP;
        float* pp = psm + h*64;

        const int  klo = lane;
        const bool hiv = (lane + 32) < N_TOK;
        const int  khi = hiv ? lane + 32 : (N_TOK-1);

        // Cache K rows for keys klo and khi as f32x2 pairs (one-time).
        u64 kk0[8], kk1[8];
        #pragma unroll
        for (int j = 0; j < 8; ++j) {
            kk0[j] = *(const u64*)(kh + klo*HDP + 2*j);
            kk1[j] = *(const u64*)(kh + khi*HDP + 2*j);
        }

        // Cache V: lane = (group g = lane>>3) x (d-pair dp = lane&7).
        // group g owns keys k = g + 4*t, t = 0..12.
        const int g  = lane >> 3;
        const int dp = lane & 7;
        u64 vc[13];
        int kidx[13];
        #pragma unroll
        for (int t = 0; t < 13; ++t) {
            const int k = g + 4*t;
            const bool val = (k < N_TOK);
            kidx[t] = val ? k : 0;
            vc[t] = val ? *(const u64*)(vh + k*HDP + 2*dp) : 0ull;
        }

        for (int r = 0; r < N_TOK; ++r) {
            // scores for keys klo, khi (pairwise f32x2 dots)
            u64 a0 = 0ull, a1 = 0ull;
            #pragma unroll
            for (int j = 0; j < 8; ++j) {
                const u64 qv = *(const u64*)(qh + r*HDP + 2*j);   // broadcast
                fma2(a0, qv, kk0[j]);
                fma2(a1, qv, kk1[j]);
            }
            float e0, o0, e1, o1;
            unpack2(a0, e0, o0);
            unpack2(a1, e1, o1);
            float s0 = (e0 + o0) * 0.25f;                          // scale = hd^-0.5
            float s1 = hiv ? (e1 + o1) * 0.25f : -FLT_MAX;
            // softmax over 49 scores (2 per lane)
            float m = fmaxf(s0, s1);
            #pragma unroll
            for (int o = 16; o > 0; o >>= 1)
                m = fmaxf(m, __shfl_xor_sync(0xffffffffu, m, o));
            float p0 = __expf(s0 - m);
            float p1 = hiv ? __expf(s1 - m) : 0.f;
            float s = p0 + p1;
            #pragma unroll
            for (int o = 16; o > 0; o >>= 1)
                s += __shfl_xor_sync(0xffffffffu, s, o);
            const float inv = __fdividef(1.0f, s);
            pp[lane] = p0 * inv;
            if (hiv) pp[lane + 32] = p1 * inv;
            __syncwarp();
            // P @ V with register V: av = sum_t p[kidx[t]] * vc[t]
            u64 av = 0ull;
            #pragma unroll
            for (int t = 0; t < 13; ++t) {
                fma2(av, bcast2(pp[kidx[t]]), vc[t]);
            }
            // reduce across the 4 key-groups (lane bits 3 and 4)
            av = add2(av, __shfl_xor_sync(0xffffffffu, av, 8));
            av = add2(av, __shfl_xor_sync(0xffffffffu, av, 16));
            if (lane < 8)
                *(u64*)(xn + r*CC + h*HDD + 2*dp) = av;
            __syncwarp();
        }
    }
    __syncthreads();

    // ---------------- Phase D: out projection + window merge  (FFMA2) ----------------
    {
        const float4 bias = *(const float4*)(b_out + 4*lane);
        u64 accA[7], accB[7];
        const u64 bA = pack2(bias.x, bias.y), bB = pack2(bias.z, bias.w);
        #pragma unroll
        for (int i = 0; i < 7; ++i) { accA[i] = bA; accB[i] = bB; }
        const float* wp = w_out + 4*lane;
        #pragma unroll 2
        for (int k = 0; k < CC; k += 4) {
            const float4 w0 = *(const float4*)(wp + (size_t)(k+0)*CC);
            const float4 w1 = *(const float4*)(wp + (size_t)(k+1)*CC);
            const float4 w2 = *(const float4*)(wp + (size_t)(k+2)*CC);
            const float4 w3 = *(const float4*)(wp + (size_t)(k+3)*CC);
            const u64 w0a = pack2(w0.x,w0.y), w0b = pack2(w0.z,w0.w);
            const u64 w1a = pack2(w1.x,w1.y), w1b = pack2(w1.z,w1.w);
            const u64 w2a = pack2(w2.x,w2.y), w2b = pack2(w2.z,w2.w);
            const u64 w3a = pack2(w3.x,w3.y), w3b = pack2(w3.z,w3.w);
            #pragma unroll
            for (int i = 0; i < 7; ++i) {
                const float4 a4 = *(const float4*)(xn + rr[i]*CC + k);
                u64 t;
                t = bcast2(a4.x); fma2(accA[i], t, w0a); fma2(accB[i], t, w0b);
                t = bcast2(a4.y); fma2(accA[i], t, w1a); fma2(accB[i], t, w1b);
                t = bcast2(a4.z); fma2(accA[i], t, w2a); fma2(accB[i], t, w2b);
                t = bcast2(a4.w); fma2(accA[i], t, w3a); fma2(accB[i], t, w3b);
            }
        }
        #pragma unroll
        for (int i = 0; i < 7; ++i) {
            const int r = wrp + 8*i;
            if (r < N_TOK) {
                const int ti = r / 7, tj = r - ti*7;
                const int n  = (wr*7 + ti)*56 + (wc*7 + tj);
                float4 o4;
                unpack2(accA[i], o4.x, o4.y);
                unpack2(accB[i], o4.z, o4.w);
                *(float4*)(out + gbase + (size_t)n*CC + 4*lane) = o4;
            }
        }
    }
}

extern "C" void kernel_launch(void* const* d_in, const int* in_sizes, int n_in,
                              void* d_out, int out_size)
{
    const float* x     = (const float*)d_in[0];
    const float* ln_g  = (const float*)d_in[1];
    const float* ln_b  = (const float*)d_in[2];
    const float* w_qkv = (const float*)d_in[3];
    const float* b_qkv = (const float*)d_in[4];
    const float* w_out = (const float*)d_in[5];
    const float* b_out = (const float*)d_in[6];
    float* out = (float*)d_out;

    const int smem_bytes = SMEM_FLOATS * (int)sizeof(float);
    cudaFuncSetAttribute(swin_fused_kernel,
                         cudaFuncAttributeMaxDynamicSharedMemorySize, smem_bytes);
    swin_fused_kernel<<<4096, 256, smem_bytes>>>(x, ln_g, ln_b, w_qkv, b_qkv,
                                                 w_out, b_out, out);
}

// round 6
// speedup vs baseline: 1.4630x; 1.1270x over previous
#include <cuda_runtime.h>
#include <math.h>
#include <float.h>

// Swin window attention, fully fused: LN -> QKV -> MHA(8 heads, hd=16) -> out proj.
// One CTA per 7x7 window (4096 CTAs), 256 threads, 2 CTAs/SM.
// GEMMs use packed fma.rn.f32x2; attention keeps K and V in registers,
// softmax processes 2 rows interleaved, probs distributed via shfl (no smem).

#define N_TOK 49     // tokens per window
#define CC    128    // channels
#define C3    384    // 3*C
#define NHH   8      // heads
#define HDD   16     // head dim
#define HDP   18     // padded head-dim stride (even -> 8B-aligned pair loads)

#define SMEM_FLOATS (N_TOK*CC + 3*NHH*N_TOK*HDP)

typedef unsigned long long u64;

__device__ __forceinline__ u64 pack2(float x, float y) {
    u64 r; asm("mov.b64 %0, {%1, %2};" : "=l"(r) : "f"(x), "f"(y)); return r;
}
__device__ __forceinline__ u64 bcast2(float x) {
    u64 r; asm("mov.b64 %0, {%1, %1};" : "=l"(r) : "f"(x)); return r;
}
__device__ __forceinline__ void unpack2(u64 v, float& x, float& y) {
    asm("mov.b64 {%0, %1}, %2;" : "=f"(x), "=f"(y) : "l"(v));
}
__device__ __forceinline__ void fma2(u64& d, u64 a, u64 b) {
    asm("fma.rn.f32x2 %0, %1, %2, %3;" : "=l"(d) : "l"(a), "l"(b), "l"(d));
}
__device__ __forceinline__ u64 add2(u64 a, u64 b) {
    u64 r; asm("add.rn.f32x2 %0, %1, %2;" : "=l"(r) : "l"(a), "l"(b)); return r;
}
__device__ __forceinline__ u64 mul2(u64 a, u64 b) {
    u64 r; asm("mul.rn.f32x2 %0, %1, %2;" : "=l"(r) : "l"(a), "l"(b)); return r;
}

__global__ void __launch_bounds__(256, 2)
swin_fused_kernel(const float* __restrict__ x,
                  const float* __restrict__ ln_g,
                  const float* __restrict__ ln_b,
                  const float* __restrict__ w_qkv,
                  const float* __restrict__ b_qkv,
                  const float* __restrict__ w_out,
                  const float* __restrict__ b_out,
                  float* __restrict__ out)
{
    extern __shared__ float sm[];
    float* xn   = sm;                         // [49][128]  (xn, later attn output)
    float* qkvs = sm + N_TOK*CC;              // [3][8][49][18]

    const int tid  = threadIdx.x;
    const int lane = tid & 31;
    const int wrp  = tid >> 5;

    const int w  = blockIdx.x;
    const int b  = w >> 6;
    const int wi = w & 63;
    const int wr = wi >> 3;
    const int wc = wi & 7;
    const size_t gbase = (size_t)b * (3136 * 128);

    // ---------------- Phase A: gather window + LayerNorm ----------------
    {
        const float4 gv = *(const float4*)(ln_g + 4*lane);
        const float4 bv = *(const float4*)(ln_b + 4*lane);
        for (int t = wrp; t < N_TOK; t += 8) {
            const int ti = t / 7, tj = t - ti*7;
            const int n  = (wr*7 + ti)*56 + (wc*7 + tj);
            const float4 xv = *(const float4*)(x + gbase + (size_t)n*CC + 4*lane);
            float s1 = xv.x + xv.y + xv.z + xv.w;
            float s2 = xv.x*xv.x + xv.y*xv.y + xv.z*xv.z + xv.w*xv.w;
            #pragma unroll
            for (int o = 16; o > 0; o >>= 1) {
                s1 += __shfl_xor_sync(0xffffffffu, s1, o);
                s2 += __shfl_xor_sync(0xffffffffu, s2, o);
            }
            const float mu   = s1 * (1.0f/128.0f);
            const float var  = fmaxf(s2 * (1.0f/128.0f) - mu*mu, 0.0f);
            const float rstd = rsqrtf(var + 1e-5f);
            float4 o4;
            o4.x = (xv.x - mu)*rstd*gv.x + bv.x;
            o4.y = (xv.y - mu)*rstd*gv.y + bv.y;
            o4.z = (xv.z - mu)*rstd*gv.z + bv.z;
            o4.w = (xv.w - mu)*rstd*gv.w + bv.w;
            *(float4*)(xn + t*CC + 4*lane) = o4;
        }
    }
    __syncthreads();

    // Row assignment for the GEMM phases: warp wrp owns rows wrp, wrp+8, ...
    int rr[7];
    #pragma unroll
    for (int i = 0; i < 7; ++i) { int r = wrp + 8*i; rr[i] = (r < N_TOK) ? r : (N_TOK-1); }

    // ---------------- Phase B: QKV GEMM  [49,128]@[128,384]+b  (FFMA2) ----------------
    const int hh = lane >> 2;          // head of this thread's 4 columns
    const int dd = (lane & 3) << 2;    // head-dim offset
    #pragma unroll
    for (int jt = 0; jt < 3; ++jt) {   // jt: 0=q, 1=k, 2=v
        const float4 bias = *(const float4*)(b_qkv + jt*CC + 4*lane);
        u64 accA[7], accB[7];
        const u64 bA = pack2(bias.x, bias.y), bB = pack2(bias.z, bias.w);
        #pragma unroll
        for (int i = 0; i < 7; ++i) { accA[i] = bA; accB[i] = bB; }
        const float* wp = w_qkv + jt*CC + 4*lane;
        #pragma unroll 2
        for (int k = 0; k < CC; k += 4) {
            const float4 w0 = *(const float4*)(wp + (size_t)(k+0)*C3);
            const float4 w1 = *(const float4*)(wp + (size_t)(k+1)*C3);
            const float4 w2 = *(const float4*)(wp + (size_t)(k+2)*C3);
            const float4 w3 = *(const float4*)(wp + (size_t)(k+3)*C3);
            const u64 w0a = pack2(w0.x,w0.y), w0b = pack2(w0.z,w0.w);
            const u64 w1a = pack2(w1.x,w1.y), w1b = pack2(w1.z,w1.w);
            const u64 w2a = pack2(w2.x,w2.y), w2b = pack2(w2.z,w2.w);
            const u64 w3a = pack2(w3.x,w3.y), w3b = pack2(w3.z,w3.w);
            #pragma unroll
            for (int i = 0; i < 7; ++i) {
                const float4 a4 = *(const float4*)(xn + rr[i]*CC + k);
                u64 t;
                t = bcast2(a4.x); fma2(accA[i], t, w0a); fma2(accB[i], t, w0b);
                t = bcast2(a4.y); fma2(accA[i], t, w1a); fma2(accB[i], t, w1b);
                t = bcast2(a4.z); fma2(accA[i], t, w2a); fma2(accB[i], t, w2b);
                t = bcast2(a4.w); fma2(accA[i], t, w3a); fma2(accB[i], t, w3b);
            }
        }
        float* qb = qkvs + (size_t)((jt*NHH + hh)*N_TOK)*HDP + dd;
        #pragma unroll
        for (int i = 0; i < 7; ++i) {
            if (wrp + 8*i < N_TOK) {
                float* p = qb + rr[i]*HDP;
                unpack2(accA[i], p[0], p[1]);
                unpack2(accB[i], p[2], p[3]);
            }
        }
    }
    __syncthreads();

    // ---------------- Phase C: attention, one warp per head, K/V in regs,
    //                  2 rows interleaved, shfl-distributed probs ----------------
    {
        const int h = wrp;
        const float* qh = qkvs + (size_t)((0*NHH + h)*N_TOK)*HDP;
        const float* kh = qkvs + (size_t)((1*NHH + h)*N_TOK)*HDP;
        const float* vh = qkvs + (size_t)((2*NHH + h)*N_TOK)*HDP;

        const int  klo = lane;
        const bool hiv = (lane + 32) < N_TOK;
        const int  khi = hiv ? lane + 32 : (N_TOK-1);

        // Cache K rows for keys klo and khi as f32x2 pairs (one-time).
        u64 kk0[8], kk1[8];
        #pragma unroll
        for (int j = 0; j < 8; ++j) {
            kk0[j] = *(const u64*)(kh + klo*HDP + 2*j);
            kk1[j] = *(const u64*)(kh + khi*HDP + 2*j);
        }

        // Cache V: lane = (group g = lane>>3) x (d-pair dp = lane&7).
        // group g owns keys k = g + 4*t, t = 0..12.
        const int g  = lane >> 3;
        const int dp = lane & 7;
        u64 vc[13];
        #pragma unroll
        for (int t = 0; t < 13; ++t) {
            const int k = g + 4*t;
            vc[t] = (k < N_TOK) ? *(const u64*)(vh + k*HDP + 2*dp) : 0ull;
        }
        // shfl source lane for prob of key g+4t (t<8 -> p0 of lane k; t>=8 -> p1 of lane k-32)
        int src[13];
        #pragma unroll
        for (int t = 0; t < 13; ++t) src[t] = (g + 4*t) & 31;

        for (int r = 0; r < N_TOK; r += 2) {
            const int r2 = (r + 1 < N_TOK) ? r + 1 : N_TOK - 1;
            // scores for keys klo, khi of rows r and r2 (4 independent chains)
            u64 aA0 = 0ull, aA1 = 0ull, aB0 = 0ull, aB1 = 0ull;
            #pragma unroll
            for (int j = 0; j < 8; ++j) {
                const u64 qA = *(const u64*)(qh + r *HDP + 2*j);   // broadcast
                const u64 qB = *(const u64*)(qh + r2*HDP + 2*j);   // broadcast
                fma2(aA0, qA, kk0[j]);
                fma2(aA1, qA, kk1[j]);
                fma2(aB0, qB, kk0[j]);
                fma2(aB1, qB, kk1[j]);
            }
            float e, o;
            unpack2(aA0, e, o);  float sA0 = (e + o) * 0.25f;
            unpack2(aA1, e, o);  float sA1 = hiv ? (e + o) * 0.25f : -FLT_MAX;
            unpack2(aB0, e, o);  float sB0 = (e + o) * 0.25f;
            unpack2(aB1, e, o);  float sB1 = hiv ? (e + o) * 0.25f : -FLT_MAX;
            // max over 49 scores, both rows interleaved
            float mA = fmaxf(sA0, sA1);
            float mB = fmaxf(sB0, sB1);
            #pragma unroll
            for (int off = 16; off > 0; off >>= 1) {
                mA = fmaxf(mA, __shfl_xor_sync(0xffffffffu, mA, off));
                mB = fmaxf(mB, __shfl_xor_sync(0xffffffffu, mB, off));
            }
            float pA0 = __expf(sA0 - mA);
            float pA1 = hiv ? __expf(sA1 - mA) : 0.f;
            float pB0 = __expf(sB0 - mB);
            float pB1 = hiv ? __expf(sB1 - mB) : 0.f;
            float uA = pA0 + pA1;
            float uB = pB0 + pB1;
            #pragma unroll
            for (int off = 16; off > 0; off >>= 1) {
                uA += __shfl_xor_sync(0xffffffffu, uA, off);
                uB += __shfl_xor_sync(0xffffffffu, uB, off);
            }
            const float invA = __fdividef(1.0f, uA);
            const float invB = __fdividef(1.0f, uB);
            // P @ V with register V; probs fetched via shfl (un-normalized)
            u64 avA = 0ull, avB = 0ull;
            #pragma unroll
            for (int t = 0; t < 13; ++t) {
                const float pa = (t < 8) ? __shfl_sync(0xffffffffu, pA0, src[t])
                                         : __shfl_sync(0xffffffffu, pA1, src[t]);
                const float pb = (t < 8) ? __shfl_sync(0xffffffffu, pB0, src[t])
                                         : __shfl_sync(0xffffffffu, pB1, src[t]);
                fma2(avA, bcast2(pa), vc[t]);
                fma2(avB, bcast2(pb), vc[t]);
            }
            // reduce across the 4 key-groups (lane bits 3 and 4), then normalize
            avA = add2(avA, __shfl_xor_sync(0xffffffffu, avA, 8));
            avB = add2(avB, __shfl_xor_sync(0xffffffffu, avB, 8));
            avA = add2(avA, __shfl_xor_sync(0xffffffffu, avA, 16));
            avB = add2(avB, __shfl_xor_sync(0xffffffffu, avB, 16));
            avA = mul2(avA, bcast2(invA));
            avB = mul2(avB, bcast2(invB));
            if (lane < 8) {
                *(u64*)(xn + r*CC + h*HDD + 2*dp) = avA;
                if (r + 1 < N_TOK)
                    *(u64*)(xn + r2*CC + h*HDD + 2*dp) = avB;
            }
        }
    }
    __syncthreads();

    // ---------------- Phase D: out projection + window merge  (FFMA2) ----------------
    {
        const float4 bias = *(const float4*)(b_out + 4*lane);
        u64 accA[7], accB[7];
        const u64 bA = pack2(bias.x, bias.y), bB = pack2(bias.z, bias.w);
        #pragma unroll
        for (int i = 0; i < 7; ++i) { accA[i] = bA; accB[i] = bB; }
        const float* wp = w_out + 4*lane;
        #pragma unroll 2
        for (int k = 0; k < CC; k += 4) {
            const float4 w0 = *(const float4*)(wp + (size_t)(k+0)*CC);
            const float4 w1 = *(const float4*)(wp + (size_t)(k+1)*CC);
            const float4 w2 = *(const float4*)(wp + (size_t)(k+2)*CC);
            const float4 w3 = *(const float4*)(wp + (size_t)(k+3)*CC);
            const u64 w0a = pack2(w0.x,w0.y), w0b = pack2(w0.z,w0.w);
            const u64 w1a = pack2(w1.x,w1.y), w1b = pack2(w1.z,w1.w);
            const u64 w2a = pack2(w2.x,w2.y), w2b = pack2(w2.z,w2.w);
            const u64 w3a = pack2(w3.x,w3.y), w3b = pack2(w3.z,w3.w);
            #pragma unroll
            for (int i = 0; i < 7; ++i) {
                const float4 a4 = *(const float4*)(xn + rr[i]*CC + k);
                u64 t;
                t = bcast2(a4.x); fma2(accA[i], t, w0a); fma2(accB[i], t, w0b);
                t = bcast2(a4.y); fma2(accA[i], t, w1a); fma2(accB[i], t, w1b);
                t = bcast2(a4.z); fma2(accA[i], t, w2a); fma2(accB[i], t, w2b);
                t = bcast2(a4.w); fma2(accA[i], t, w3a); fma2(accB[i], t, w3b);
            }
        }
        #pragma unroll
        for (int i = 0; i < 7; ++i) {
            const int r = wrp + 8*i;
            if (r < N_TOK) {
                const int ti = r / 7, tj = r - ti*7;
                const int n  = (wr*7 + ti)*56 + (wc*7 + tj);
                float4 o4;
                unpack2(accA[i], o4.x, o4.y);
                unpack2(accB[i], o4.z, o4.w);
                *(float4*)(out + gbase + (size_t)n*CC + 4*lane) = o4;
            }
        }
    }
}

extern "C" void kernel_launch(void* const* d_in, const int* in_sizes, int n_in,
                              void* d_out, int out_size)
{
    const float* x     = (const float*)d_in[0];
    const float* ln_g  = (const float*)d_in[1];
    const float* ln_b  = (const float*)d_in[2];
    const float* w_qkv = (const float*)d_in[3];
    const float* b_qkv = (const float*)d_in[4];
    const float* w_out = (const float*)d_in[5];
    const float* b_out = (const float*)d_in[6];
    float* out = (float*)d_out;

    const int smem_bytes = SMEM_FLOATS * (int)sizeof(float);
    cudaFuncSetAttribute(swin_fused_kernel,
                         cudaFuncAttributeMaxDynamicSharedMemorySize, smem_bytes);
    swin_fused_kernel<<<4096, 256, smem_bytes>>>(x, ln_g, ln_b, w_qkv, b_qkv,
                                                 w_out, b_out, out);
}

// round 8
// speedup vs baseline: 1.5233x; 1.0412x over previous
#include <cuda_runtime.h>
#include <math.h>
#include <float.h>

// Swin window attention, fully fused: LN -> QKV -> MHA(8 heads, hd=16) -> out proj.
// One CTA per 7x7 window (4096 CTAs), 256 threads, 2 CTAs/SM.
// GEMMs use packed fma.rn.f32x2 with 2-deep register-pipelined weight prefetch
// (weights come from L2: smem carveout leaves no L1D). Attention keeps K and V
// in registers, 2 rows interleaved, shfl-distributed probs.

#define N_TOK 49     // tokens per window
#define CC    128    // channels
#define C3    384    // 3*C
#define NHH   8      // heads
#define HDD   16     // head dim
#define HDP   18     // padded head-dim stride (even -> 8B-aligned pair loads)

#define SMEM_FLOATS (N_TOK*CC + 3*NHH*N_TOK*HDP)

typedef unsigned long long u64;

__device__ __forceinline__ u64 pack2(float x, float y) {
    u64 r; asm("mov.b64 %0, {%1, %2};" : "=l"(r) : "f"(x), "f"(y)); return r;
}
__device__ __forceinline__ u64 bcast2(float x) {
    u64 r; asm("mov.b64 %0, {%1, %1};" : "=l"(r) : "f"(x)); return r;
}
__device__ __forceinline__ void unpack2(u64 v, float& x, float& y) {
    asm("mov.b64 {%0, %1}, %2;" : "=f"(x), "=f"(y) : "l"(v));
}
__device__ __forceinline__ void fma2(u64& d, u64 a, u64 b) {
    asm("fma.rn.f32x2 %0, %1, %2, %3;" : "=l"(d) : "l"(a), "l"(b), "l"(d));
}
__device__ __forceinline__ u64 add2(u64 a, u64 b) {
    u64 r; asm("add.rn.f32x2 %0, %1, %2;" : "=l"(r) : "l"(a), "l"(b)); return r;
}
__device__ __forceinline__ u64 mul2(u64 a, u64 b) {
    u64 r; asm("mul.rn.f32x2 %0, %1, %2;" : "=l"(r) : "l"(a), "l"(b)); return r;
}

// One 4-k compute block: acc[7][2] += a(rows, k..k+3) * w(k..k+3, 4 cols)
__device__ __forceinline__ void gemm_block(const float* __restrict__ xn,
                                           const int* rr, int kbase,
                                           const float4& w0, const float4& w1,
                                           const float4& w2, const float4& w3,
                                           u64* accA, u64* accB)
{
    const u64 w0a = pack2(w0.x,w0.y), w0b = pack2(w0.z,w0.w);
    const u64 w1a = pack2(w1.x,w1.y), w1b = pack2(w1.z,w1.w);
    const u64 w2a = pack2(w2.x,w2.y), w2b = pack2(w2.z,w2.w);
    const u64 w3a = pack2(w3.x,w3.y), w3b = pack2(w3.z,w3.w);
    #pragma unroll
    for (int i = 0; i < 7; ++i) {
        const float4 a4 = *(const float4*)(xn + rr[i]*CC + kbase);
        u64 t;
        t = bcast2(a4.x); fma2(accA[i], t, w0a); fma2(accB[i], t, w0b);
        t = bcast2(a4.y); fma2(accA[i], t, w1a); fma2(accB[i], t, w1b);
        t = bcast2(a4.z); fma2(accA[i], t, w2a); fma2(accB[i], t, w2b);
        t = bcast2(a4.w); fma2(accA[i], t, w3a); fma2(accB[i], t, w3b);
    }
}

__global__ void __launch_bounds__(256, 2)
swin_fused_kernel(const float* __restrict__ x,
                  const float* __restrict__ ln_g,
                  const float* __restrict__ ln_b,
                  const float* __restrict__ w_qkv,
                  const float* __restrict__ b_qkv,
                  const float* __restrict__ w_out,
                  const float* __restrict__ b_out,
                  float* __restrict__ out)
{
    extern __shared__ float sm[];
    float* xn   = sm;                         // [49][128]  (xn, later attn output)
    float* qkvs = sm + N_TOK*CC;              // [3][8][49][18]

    const int tid  = threadIdx.x;
    const int lane = tid & 31;
    const int wrp  = tid >> 5;

    const int w  = blockIdx.x;
    const int b  = w >> 6;
    const int wi = w & 63;
    const int wr = wi >> 3;
    const int wc = wi & 7;
    const size_t gbase = (size_t)b * (3136 * 128);

    // ---------------- Phase A: gather window + LayerNorm ----------------
    {
        const float4 gv = *(const float4*)(ln_g + 4*lane);
        const float4 bv = *(const float4*)(ln_b + 4*lane);
        for (int t = wrp; t < N_TOK; t += 8) {
            const int ti = t / 7, tj = t - ti*7;
            const int n  = (wr*7 + ti)*56 + (wc*7 + tj);
            const float4 xv = *(const float4*)(x + gbase + (size_t)n*CC + 4*lane);
            float s1 = xv.x + xv.y + xv.z + xv.w;
            float s2 = xv.x*xv.x + xv.y*xv.y + xv.z*xv.z + xv.w*xv.w;
            #pragma unroll
            for (int o = 16; o > 0; o >>= 1) {
                s1 += __shfl_xor_sync(0xffffffffu, s1, o);
                s2 += __shfl_xor_sync(0xffffffffu, s2, o);
            }
            const float mu   = s1 * (1.0f/128.0f);
            const float var  = fmaxf(s2 * (1.0f/128.0f) - mu*mu, 0.0f);
            const float rstd = rsqrtf(var + 1e-5f);
            float4 o4;
            o4.x = (xv.x - mu)*rstd*gv.x + bv.x;
            o4.y = (xv.y - mu)*rstd*gv.y + bv.y;
            o4.z = (xv.z - mu)*rstd*gv.z + bv.z;
            o4.w = (xv.w - mu)*rstd*gv.w + bv.w;
            *(float4*)(xn + t*CC + 4*lane) = o4;
        }
    }
    __syncthreads();

    // Row assignment for the GEMM phases: warp wrp owns rows wrp, wrp+8, ...
    int rr[7];
    #pragma unroll
    for (int i = 0; i < 7; ++i) { int r = wrp + 8*i; rr[i] = (r < N_TOK) ? r : (N_TOK-1); }

    // ---------------- Phase B: QKV GEMM  [49,128]@[128,384]+b  (FFMA2, pipelined) ----------------
    const int hh = lane >> 2;          // head of this thread's 4 columns
    const int dd = (lane & 3) << 2;    // head-dim offset
    #pragma unroll
    for (int jt = 0; jt < 3; ++jt) {   // jt: 0=q, 1=k, 2=v
        const float4 bias = *(const float4*)(b_qkv + jt*CC + 4*lane);
        u64 accA[7], accB[7];
        const u64 bA = pack2(bias.x, bias.y), bB = pack2(bias.z, bias.w);
        #pragma unroll
        for (int i = 0; i < 7; ++i) { accA[i] = bA; accB[i] = bB; }
        const float* wp = w_qkv + jt*CC + 4*lane;

        float4 wA0, wA1, wA2, wA3, wB0, wB1, wB2, wB3;
        wA0 = *(const float4*)(wp + 0*(size_t)C3);
        wA1 = *(const float4*)(wp + 1*(size_t)C3);
        wA2 = *(const float4*)(wp + 2*(size_t)C3);
        wA3 = *(const float4*)(wp + 3*(size_t)C3);
        #pragma unroll 1
        for (int k = 0; k < CC; k += 8) {
            {   // prefetch k+4..k+7
                const float* wq = wp + (size_t)(k+4)*C3;
                wB0 = *(const float4*)(wq + 0*(size_t)C3);
                wB1 = *(const float4*)(wq + 1*(size_t)C3);
                wB2 = *(const float4*)(wq + 2*(size_t)C3);
                wB3 = *(const float4*)(wq + 3*(size_t)C3);
            }
            gemm_block(xn, rr, k, wA0, wA1, wA2, wA3, accA, accB);
            if (k + 8 < CC) {   // prefetch k+8..k+11
                const float* wq = wp + (size_t)(k+8)*C3;
                wA0 = *(const float4*)(wq + 0*(size_t)C3);
                wA1 = *(const float4*)(wq + 1*(size_t)C3);
                wA2 = *(const float4*)(wq + 2*(size_t)C3);
                wA3 = *(const float4*)(wq + 3*(size_t)C3);
            }
            gemm_block(xn, rr, k+4, wB0, wB1, wB2, wB3, accA, accB);
        }
        float* qb = qkvs + (size_t)((jt*NHH + hh)*N_TOK)*HDP + dd;
        #pragma unroll
        for (int i = 0; i < 7; ++i) {
            if (wrp + 8*i < N_TOK) {
                float* p = qb + rr[i]*HDP;
                unpack2(accA[i], p[0], p[1]);
                unpack2(accB[i], p[2], p[3]);
            }
        }
    }
    __syncthreads();

    // ---------------- Phase C: attention, one warp per head, K/V in regs,
    //                  2 rows interleaved, shfl-distributed probs ----------------
    {
        const int h = wrp;
        const float* qh = qkvs + (size_t)((0*NHH + h)*N_TOK)*HDP;
        const float* kh = qkvs + (size_t)((1*NHH + h)*N_TOK)*HDP;
        const float* vh = qkvs + (size_t)((2*NHH + h)*N_TOK)*HDP;

        const int  klo = lane;
        const bool hiv = (lane + 32) < N_TOK;
        const int  khi = hiv ? lane + 32 : (N_TOK-1);

        // Cache K rows for keys klo and khi as f32x2 pairs (one-time).
        u64 kk0[8], kk1[8];
        #pragma unroll
        for (int j = 0; j < 8; ++j) {
            kk0[j] = *(const u64*)(kh + klo*HDP + 2*j);
            kk1[j] = *(const u64*)(kh + khi*HDP + 2*j);
        }

        // Cache V: lane = (group g = lane>>3) x (d-pair dp = lane&7).
        // group g owns keys k = g + 4*t, t = 0..12.
        const int g  = lane >> 3;
        const int dp = lane & 7;
        u64 vc[13];
        #pragma unroll
        for (int t = 0; t < 13; ++t) {
            const int k = g + 4*t;
            vc[t] = (k < N_TOK) ? *(const u64*)(vh + k*HDP + 2*dp) : 0ull;
        }
        // shfl source lane for prob of key g+4t (t<8 -> p0 of lane k; t>=8 -> p1 of lane k-32)
        int src[13];
        #pragma unroll
        for (int t = 0; t < 13; ++t) src[t] = (g + 4*t) & 31;

        for (int r = 0; r < N_TOK; r += 2) {
            const int r2 = (r + 1 < N_TOK) ? r + 1 : N_TOK - 1;
            // scores for keys klo, khi of rows r and r2 (4 independent chains)
            u64 aA0 = 0ull, aA1 = 0ull, aB0 = 0ull, aB1 = 0ull;
            #pragma unroll
            for (int j = 0; j < 8; ++j) {
                const u64 qA = *(const u64*)(qh + r *HDP + 2*j);   // broadcast
                const u64 qB = *(const u64*)(qh + r2*HDP + 2*j);   // broadcast
                fma2(aA0, qA, kk0[j]);
                fma2(aA1, qA, kk1[j]);
                fma2(aB0, qB, kk0[j]);
                fma2(aB1, qB, kk1[j]);
            }
            float e, o;
            unpack2(aA0, e, o);  float sA0 = (e + o) * 0.25f;
            unpack2(aA1, e, o);  float sA1 = hiv ? (e + o) * 0.25f : -FLT_MAX;
            unpack2(aB0, e, o);  float sB0 = (e + o) * 0.25f;
            unpack2(aB1, e, o);  float sB1 = hiv ? (e + o) * 0.25f : -FLT_MAX;
            // max over 49 scores, both rows interleaved
            float mA = fmaxf(sA0, sA1);
            float mB = fmaxf(sB0, sB1);
            #pragma unroll
            for (int off = 16; off > 0; off >>= 1) {
                mA = fmaxf(mA, __shfl_xor_sync(0xffffffffu, mA, off));
                mB = fmaxf(mB, __shfl_xor_sync(0xffffffffu, mB, off));
            }
            float pA0 = __expf(sA0 - mA);
            float pA1 = hiv ? __expf(sA1 - mA) : 0.f;
            float pB0 = __expf(sB0 - mB);
            float pB1 = hiv ? __expf(sB1 - mB) : 0.f;
            float uA = pA0 + pA1;
            float uB = pB0 + pB1;
            #pragma unroll
            for (int off = 16; off > 0; off >>= 1) {
                uA += __shfl_xor_sync(0xffffffffu, uA, off);
                uB += __shfl_xor_sync(0xffffffffu, uB, off);
            }
            const float invA = __fdividef(1.0f, uA);
            const float invB = __fdividef(1.0f, uB);
            // P @ V with register V; probs fetched via shfl (un-normalized)
            u64 avA = 0ull, avB = 0ull;
            #pragma unroll
            for (int t = 0; t < 13; ++t) {
                const float pa = (t < 8) ? __shfl_sync(0xffffffffu, pA0, src[t])
                                         : __shfl_sync(0xffffffffu, pA1, src[t]);
                const float pb = (t < 8) ? __shfl_sync(0xffffffffu, pB0, src[t])
                                         : __shfl_sync(0xffffffffu, pB1, src[t]);
                fma2(avA, bcast2(pa), vc[t]);
                fma2(avB, bcast2(pb), vc[t]);
            }
            // reduce across the 4 key-groups (lane bits 3 and 4), then normalize
            avA = add2(avA, __shfl_xor_sync(0xffffffffu, avA, 8));
            avB = add2(avB, __shfl_xor_sync(0xffffffffu, avB, 8));
            avA = add2(avA, __shfl_xor_sync(0xffffffffu, avA, 16));
            avB = add2(avB, __shfl_xor_sync(0xffffffffu, avB, 16));
            avA = mul2(avA, bcast2(invA));
            avB = mul2(avB, bcast2(invB));
            if (lane < 8) {
                *(u64*)(xn + r*CC + h*HDD + 2*dp) = avA;
                if (r + 1 < N_TOK)
                    *(u64*)(xn + r2*CC + h*HDD + 2*dp) = avB;
            }
        }
    }
    __syncthreads();

    // ---------------- Phase D: out projection + window merge  (FFMA2, pipelined) ----------------
    {
        const float4 bias = *(const float4*)(b_out + 4*lane);
        u64 accA[7], accB[7];
        const u64 bA = pack2(bias.x, bias.y), bB = pack2(bias.z, bias.w);
        #pragma unroll
        for (int i = 0; i < 7; ++i) { accA[i] = bA; accB[i] = bB; }
        const float* wp = w_out + 4*lane;

        float4 wA0, wA1, wA2, wA3, wB0, wB1, wB2, wB3;
        wA0 = *(const float4*)(wp + 0*(size_t)CC);
        wA1 = *(const float4*)(wp + 1*(size_t)CC);
        wA2 = *(const float4*)(wp + 2*(size_t)CC);
        wA3 = *(const float4*)(wp + 3*(size_t)CC);
        #pragma unroll 1
        for (int k = 0; k < CC; k += 8) {
            {   // prefetch k+4..k+7
                const float* wq = wp + (size_t)(k+4)*CC;
                wB0 = *(const float4*)(wq + 0*(size_t)CC);
                wB1 = *(const float4*)(wq + 1*(size_t)CC);
                wB2 = *(const float4*)(wq + 2*(size_t)CC);
                wB3 = *(const float4*)(wq + 3*(size_t)CC);
            }
            gemm_block(xn, rr, k, wA0, wA1, wA2, wA3, accA, accB);
            if (k + 8 < CC) {   // prefetch k+8..k+11
                const float* wq = wp + (size_t)(k+8)*CC;
                wA0 = *(const float4*)(wq + 0*(size_t)CC);
                wA1 = *(const float4*)(wq + 1*(size_t)CC);
                wA2 = *(const float4*)(wq + 2*(size_t)CC);
                wA3 = *(const float4*)(wq + 3*(size_t)CC);
            }
            gemm_block(xn, rr, k+4, wB0, wB1, wB2, wB3, accA, accB);
        }
        #pragma unroll
        for (int i = 0; i < 7; ++i) {
            const int r = wrp + 8*i;
            if (r < N_TOK) {
                const int ti = r / 7, tj = r - ti*7;
                const int n  = (wr*7 + ti)*56 + (wc*7 + tj);
                float4 o4;
                unpack2(accA[i], o4.x, o4.y);
                unpack2(accB[i], o4.z, o4.w);
                *(float4*)(out + gbase + (size_t)n*CC + 4*lane) = o4;
            }
        }
    }
}

extern "C" void kernel_launch(void* const* d_in, const int* in_sizes, int n_in,
                              void* d_out, int out_size)
{
    const float* x     = (const float*)d_in[0];
    const float* ln_g  = (const float*)d_in[1];
    const float* ln_b  = (const float*)d_in[2];
    const float* w_qkv = (const float*)d_in[3];
    const float* b_qkv = (const float*)d_in[4];
    const float* w_out = (const float*)d_in[5];
    const float* b_out = (const float*)d_in[6];
    float* out = (float*)d_out;

    const int smem_bytes = SMEM_FLOATS * (int)sizeof(float);
    cudaFuncSetAttribute(swin_fused_kernel,
                         cudaFuncAttributeMaxDynamicSharedMemorySize, smem_bytes);
    swin_fused_kernel<<<4096, 256, smem_bytes>>>(x, ln_g, ln_b, w_qkv, b_qkv,
                                                 w_out, b_out, out);
}

// round 16
// speedup vs baseline: 1.9215x; 1.2614x over previous
#include <cuda_runtime.h>
#include <cuda_bf16.h>
#include <math.h>
#include <float.h>

// 3-kernel Swin window attention:
//  K1: LN + QKV GEMM (all 200704 tokens) via mma.sync bf16 hi/lo split -> g_qkv
//  K2: per-window attention (register K/V, shfl softmax)               -> g_att
//  K3: out projection GEMM + window merge scatter                      -> out

#define NWIN  4096
#define NTOK  49
#define CC    128
#define C3    384
#define NHH   8
#define HDD   16
#define HDP   18
#define MTILE 128

typedef unsigned int u32;
typedef unsigned long long u64;

__device__ float g_qkv[(size_t)NWIN*3*NHH*NTOK*HDD];   // [win][jt][h][t][d]
__device__ float g_att[(size_t)NWIN*NTOK*CC];          // [win][t][c]

// ---------------- small helpers ----------------
__device__ __forceinline__ u64 pack2(float x, float y) {
    u64 r; asm("mov.b64 %0, {%1, %2};" : "=l"(r) : "f"(x), "f"(y)); return r;
}
__device__ __forceinline__ u64 bcast2(float x) {
    u64 r; asm("mov.b64 %0, {%1, %1};" : "=l"(r) : "f"(x)); return r;
}
__device__ __forceinline__ void unpack2(u64 v, float& x, float& y) {
    asm("mov.b64 {%0, %1}, %2;" : "=f"(x), "=f"(y) : "l"(v));
}
__device__ __forceinline__ void fma2(u64& d, u64 a, u64 b) {
    asm("fma.rn.f32x2 %0, %1, %2, %3;" : "=l"(d) : "l"(a), "l"(b), "l"(d));
}
__device__ __forceinline__ u64 add2(u64 a, u64 b) {
    u64 r; asm("add.rn.f32x2 %0, %1, %2;" : "=l"(r) : "l"(a), "l"(b)); return r;
}
__device__ __forceinline__ u64 mul2(u64 a, u64 b) {
    u64 r; asm("mul.rn.f32x2 %0, %1, %2;" : "=l"(r) : "l"(a), "l"(b)); return r;
}

// split (x,y) into bf16 hi pair and bf16 lo (residual) pair; low half = x
__device__ __forceinline__ void split_pack(float x, float y, u32 &hi, u32 &lo) {
    __nv_bfloat16 hx = __float2bfloat16_rn(x);
    __nv_bfloat16 hy = __float2bfloat16_rn(y);
    float rx = x - __bfloat162float(hx);
    float ry = y - __bfloat162float(hy);
    __nv_bfloat16 lx = __float2bfloat16_rn(rx);
    __nv_bfloat16 ly = __float2bfloat16_rn(ry);
    hi = ((u32)__bfloat16_as_ushort(hy) << 16) | (u32)__bfloat16_as_ushort(hx);
    lo = ((u32)__bfloat16_as_ushort(ly) << 16) | (u32)__bfloat16_as_ushort(lx);
}

__device__ __forceinline__ void mma16816(float* d, const uint4& a, const uint2& b) {
    asm volatile("mma.sync.aligned.m16n8k16.row.col.f32.bf16.bf16.f32 "
        "{%0,%1,%2,%3}, {%4,%5,%6,%7}, {%8,%9}, {%0,%1,%2,%3};"
        : "+f"(d[0]), "+f"(d[1]), "+f"(d[2]), "+f"(d[3])
        : "r"(a.x), "r"(a.y), "r"(a.z), "r"(a.w), "r"(b.x), "r"(b.y));
}

// fragment-native smem slots (u32 index). A: [hl][mt8][ks8][lane32][4regs], B: [hl][nt8][ks8][lane32][2regs]
__device__ __forceinline__ int a_slot(int hl, int r, int c) {   // c even
    int mt = r >> 4, ks = c >> 4;
    int rp = r & 15, cp = c & 15;
    int ri = ((rp >> 3) & 1) + (((cp >> 3) & 1) << 1);
    int ln = (rp & 7) * 4 + ((cp & 7) >> 1);
    return ((hl * 64 + mt * 8 + ks) * 32 + ln) * 4 + ri;
}
__device__ __forceinline__ int b_slot(int hl, int c, int n) {   // c even
    int nt = n >> 3, ks = c >> 4;
    int cp = c & 15;
    int ri = (cp >> 3) & 1;
    int ln = (n & 7) * 4 + ((cp & 7) >> 1);
    return ((hl * 64 + nt * 8 + ks) * 32 + ln) * 2 + ri;
}

#define A_U32 16384   // 2*64*32*4
#define B_U32 8192    // 2*64*32*2
#define SM_GEMM_BYTES ((A_U32 + B_U32) * 4)

// ---------------- Kernel 1: LN + QKV GEMM ----------------
__global__ void __launch_bounds__(256)
k1_ln_qkv(const float* __restrict__ x, const float* __restrict__ ln_g,
          const float* __restrict__ ln_b, const float* __restrict__ w_qkv,
          const float* __restrict__ b_qkv)
{
    extern __shared__ u32 sh[];
    u32* Af = sh;
    u32* Bf = sh + A_U32;
    const int tid = threadIdx.x, lane = tid & 31, wrp = tid >> 5;
    const int T0 = blockIdx.x * MTILE;

    // ---- LN + bf16-split into A fragments ----
    {
        const float2 g0 = *(const float2*)(ln_g + 2*lane);
        const float2 g1 = *(const float2*)(ln_g + 64 + 2*lane);
        const float2 e0 = *(const float2*)(ln_b + 2*lane);
        const float2 e1 = *(const float2*)(ln_b + 64 + 2*lane);
        for (int r = wrp; r < MTILE; r += 8) {
            const int T = T0 + r;
            const int win = T / 49, t = T - win*49;
            const int bb = win >> 6, wi = win & 63;
            const int n = ((wi>>3)*7 + t/7)*56 + (wi&7)*7 + (t - (t/7)*7);
            const float* xr = x + ((size_t)bb*3136 + n)*CC;
            const float2 xa = *(const float2*)(xr + 2*lane);
            const float2 xb = *(const float2*)(xr + 64 + 2*lane);
            float s1 = xa.x+xa.y+xb.x+xb.y;
            float s2 = xa.x*xa.x+xa.y*xa.y+xb.x*xb.x+xb.y*xb.y;
            #pragma unroll
            for (int o=16;o>0;o>>=1){ s1 += __shfl_xor_sync(~0u,s1,o); s2 += __shfl_xor_sync(~0u,s2,o); }
            const float mu = s1*(1.f/128.f);
            const float var = fmaxf(s2*(1.f/128.f) - mu*mu, 0.f);
            const float rstd = rsqrtf(var + 1e-5f);
            const float y0 = (xa.x-mu)*rstd*g0.x + e0.x;
            const float y1 = (xa.y-mu)*rstd*g0.y + e0.y;
            const float y2 = (xb.x-mu)*rstd*g1.x + e1.x;
            const float y3 = (xb.y-mu)*rstd*g1.y + e1.y;
            u32 h, l;
            split_pack(y0, y1, h, l);
            Af[a_slot(0, r, 2*lane)] = h;        Af[a_slot(1, r, 2*lane)] = l;
            split_pack(y2, y3, h, l);
            Af[a_slot(0, r, 64 + 2*lane)] = h;   Af[a_slot(1, r, 64 + 2*lane)] = l;
        }
    }

    // epilogue row mapping (rows r0, r0+8 owned by this lane)
    const int r0 = wrp*16 + (lane>>2);
    const int TA = T0 + r0,  wA = TA/49, tA = TA - wA*49;
    const int TB = TA + 8,   wB = TB/49, tB = TB - wB*49;

    for (int nc = 0; nc < 6; ++nc) {
        __syncthreads();
        // stage B chunk: cols [nc*64, +64), k = 0..127, bf16-split
        for (int i = tid; i < 64*64; i += 256) {
            const int kp = i >> 6, n = i & 63;
            const int k = kp*2, col = nc*64 + n;
            const float wv0 = w_qkv[(size_t)k*C3 + col];
            const float wv1 = w_qkv[(size_t)(k+1)*C3 + col];
            u32 h, l; split_pack(wv0, wv1, h, l);
            Bf[b_slot(0, k, n)] = h;  Bf[b_slot(1, k, n)] = l;
        }
        __syncthreads();

        float acc[8][4];
        #pragma unroll
        for (int nt=0; nt<8; ++nt) { acc[nt][0]=acc[nt][1]=acc[nt][2]=acc[nt][3]=0.f; }
        #pragma unroll
        for (int ks = 0; ks < 8; ++ks) {
            const uint4 Ah = *(const uint4*)&Af[((0*64 + wrp*8 + ks)*32 + lane)*4];
            const uint4 Al = *(const uint4*)&Af[((1*64 + wrp*8 + ks)*32 + lane)*4];
            #pragma unroll
            for (int nt = 0; nt < 8; ++nt) {
                const uint2 Bh = *(const uint2*)&Bf[((0*64 + nt*8 + ks)*32 + lane)*2];
                const uint2 Bl = *(const uint2*)&Bf[((1*64 + nt*8 + ks)*32 + lane)*2];
                mma16816(acc[nt], Ah, Bh);
                mma16816(acc[nt], Ah, Bl);
                mma16816(acc[nt], Al, Bh);
            }
        }
        // epilogue: bias + scatter to g_qkv[win][jt][head][t][d]
        #pragma unroll
        for (int nt = 0; nt < 8; ++nt) {
            const int col = nc*64 + nt*8 + 2*(lane&3);
            const float2 bias = *(const float2*)(b_qkv + col);
            const int jt = col >> 7, rem = col & 127, hd = rem >> 4, d = rem & 15;
            float* p0 = g_qkv + (((size_t)wA*3 + jt)*NHH + hd)*(NTOK*HDD) + tA*HDD + d;
            float* p1 = g_qkv + (((size_t)wB*3 + jt)*NHH + hd)*(NTOK*HDD) + tB*HDD + d;
            float2 v0; v0.x = acc[nt][0]+bias.x; v0.y = acc[nt][1]+bias.y;
            float2 v1; v1.x = acc[nt][2]+bias.x; v1.y = acc[nt][3]+bias.y;
            *(float2*)p0 = v0;
            *(float2*)p1 = v1;
        }
    }
}

// ---------------- Kernel 2: per-window attention ----------------
__global__ void __launch_bounds__(256)
k2_attn()
{
    extern __shared__ float qkvs[];    // [3][8][49][18]
    const int tid = threadIdx.x, lane = tid & 31, wrp = tid >> 5;
    const int win = blockIdx.x;

    // stage q,k,v (dense 16-stride -> padded 18-stride)
    const float* src = g_qkv + (size_t)win*(3*NHH*NTOK*HDD);
    for (int i = tid; i < 1176*8; i += 256) {
        const int row = i >> 3, j = i & 7;
        *(u64*)(qkvs + row*HDP + 2*j) = *(const u64*)(src + row*HDD + 2*j);
    }
    __syncthreads();

    const int h = wrp;
    const float* qh = qkvs + (size_t)((0*NHH + h)*NTOK)*HDP;
    const float* kh = qkvs + (size_t)((1*NHH + h)*NTOK)*HDP;
    const float* vh = qkvs + (size_t)((2*NHH + h)*NTOK)*HDP;
    float* gout = g_att + (size_t)win*NTOK*CC;

    const int  klo = lane;
    const bool hiv = (lane + 32) < NTOK;
    const int  khi = hiv ? lane + 32 : (NTOK-1);

    u64 kk0[8], kk1[8];
    #pragma unroll
    for (int j = 0; j < 8; ++j) {
        kk0[j] = *(const u64*)(kh + klo*HDP + 2*j);
        kk1[j] = *(const u64*)(kh + khi*HDP + 2*j);
    }
    const int g  = lane >> 3;
    const int dp = lane & 7;
    u64 vc[13];
    #pragma unroll
    for (int t = 0; t < 13; ++t) {
        const int k = g + 4*t;
        vc[t] = (k < NTOK) ? *(const u64*)(vh + k*HDP + 2*dp) : 0ull;
    }
    int src_ln[13];
    #pragma unroll
    for (int t = 0; t < 13; ++t) src_ln[t] = (g + 4*t) & 31;

    for (int r = 0; r < NTOK; r += 2) {
        const int r2 = (r + 1 < NTOK) ? r + 1 : NTOK - 1;
        u64 aA0 = 0ull, aA1 = 0ull, aB0 = 0ull, aB1 = 0ull;
        #pragma unroll
        for (int j = 0; j < 8; ++j) {
            const u64 qA = *(const u64*)(qh + r *HDP + 2*j);
            const u64 qB = *(const u64*)(qh + r2*HDP + 2*j);
            fma2(aA0, qA, kk0[j]);
            fma2(aA1, qA, kk1[j]);
            fma2(aB0, qB, kk0[j]);
            fma2(aB1, qB, kk1[j]);
        }
        float e, o;
        unpack2(aA0, e, o);  float sA0 = (e + o) * 0.25f;
        unpack2(aA1, e, o);  float sA1 = hiv ? (e + o) * 0.25f : -FLT_MAX;
        unpack2(aB0, e, o);  float sB0 = (e + o) * 0.25f;
        unpack2(aB1, e, o);  float sB1 = hiv ? (e + o) * 0.25f : -FLT_MAX;
        float mA = fmaxf(sA0, sA1);
        float mB = fmaxf(sB0, sB1);
        #pragma unroll
        for (int off = 16; off > 0; off >>= 1) {
            mA = fmaxf(mA, __shfl_xor_sync(~0u, mA, off));
            mB = fmaxf(mB, __shfl_xor_sync(~0u, mB, off));
        }
        float pA0 = __expf(sA0 - mA);
        float pA1 = hiv ? __expf(sA1 - mA) : 0.f;
        float pB0 = __expf(sB0 - mB);
        float pB1 = hiv ? __expf(sB1 - mB) : 0.f;
        float uA = pA0 + pA1;
        float uB = pB0 + pB1;
        #pragma unroll
        for (int off = 16; off > 0; off >>= 1) {
            uA += __shfl_xor_sync(~0u, uA, off);
            uB += __shfl_xor_sync(~0u, uB, off);
        }
        const float invA = __fdividef(1.0f, uA);
        const float invB = __fdividef(1.0f, uB);
        u64 avA = 0ull, avB = 0ull;
        #pragma unroll
        for (int t = 0; t < 13; ++t) {
            const float pa = (t < 8) ? __shfl_sync(~0u, pA0, src_ln[t])
                                     : __shfl_sync(~0u, pA1, src_ln[t]);
            const float pb = (t < 8) ? __shfl_sync(~0u, pB0, src_ln[t])
                                     : __shfl_sync(~0u, pB1, src_ln[t]);
            fma2(avA, bcast2(pa), vc[t]);
            fma2(avB, bcast2(pb), vc[t]);
        }
        avA = add2(avA, __shfl_xor_sync(~0u, avA, 8));
        avB = add2(avB, __shfl_xor_sync(~0u, avB, 8));
        avA = add2(avA, __shfl_xor_sync(~0u, avA, 16));
        avB = add2(avB, __shfl_xor_sync(~0u, avB, 16));
        avA = mul2(avA, bcast2(invA));
        avB = mul2(avB, bcast2(invB));
        if (lane < 8) {
            *(u64*)(gout + r*CC + h*HDD + 2*dp) = avA;
            if (r + 1 < NTOK)
                *(u64*)(gout + r2*CC + h*HDD + 2*dp) = avB;
        }
    }
}

// ---------------- Kernel 3: out projection + merge ----------------
__global__ void __launch_bounds__(256)
k3_proj(const float* __restrict__ w_out, const float* __restrict__ b_out,
        float* __restrict__ out)
{
    extern __shared__ u32 sh[];
    u32* Af = sh;
    u32* Bf = sh + A_U32;
    const int tid = threadIdx.x, lane = tid & 31, wrp = tid >> 5;
    const int T0 = blockIdx.x * MTILE;

    // stage A = g_att rows, bf16-split into fragments
    for (int i = tid; i < 128*64; i += 256) {
        const int r = i >> 6, cp = i & 63;
        const float2 v = *(const float2*)(g_att + (size_t)(T0 + r)*CC + 2*cp);
        u32 h, l; split_pack(v.x, v.y, h, l);
        Af[a_slot(0, r, 2*cp)] = h;  Af[a_slot(1, r, 2*cp)] = l;
    }

    const int r0 = wrp*16 + (lane>>2);
    const int TA = T0 + r0, TB = TA + 8;
    const int wA = TA/49, tA = TA - wA*49;
    const int wB = TB/49, tB = TB - wB*49;
    const int bA = wA>>6, wiA = wA&63;
    const int nA = ((wiA>>3)*7 + tA/7)*56 + (wiA&7)*7 + (tA - (tA/7)*7);
    const int bB = wB>>6, wiB = wB&63;
    const int nB = ((wiB>>3)*7 + tB/7)*56 + (wiB&7)*7 + (tB - (tB/7)*7);
    float* oA = out + ((size_t)bA*3136 + nA)*CC;
    float* oB = out + ((size_t)bB*3136 + nB)*CC;

    for (int nc = 0; nc < 2; ++nc) {
        __syncthreads();
        for (int i = tid; i < 64*64; i += 256) {
            const int kp = i >> 6, n = i & 63;
            const int k = kp*2, col = nc*64 + n;
            const float wv0 = w_out[(size_t)k*CC + col];
            const float wv1 = w_out[(size_t)(k+1)*CC + col];
            u32 h, l; split_pack(wv0, wv1, h, l);
            Bf[b_slot(0, k, n)] = h;  Bf[b_slot(1, k, n)] = l;
        }
        __syncthreads();

        float acc[8][4];
        #pragma unroll
        for (int nt=0; nt<8; ++nt) { acc[nt][0]=acc[nt][1]=acc[nt][2]=acc[nt][3]=0.f; }
        #pragma unroll
        for (int ks = 0; ks < 8; ++ks) {
            const uint4 Ah = *(const uint4*)&Af[((0*64 + wrp*8 + ks)*32 + lane)*4];
            const uint4 Al = *(const uint4*)&Af[((1*64 + wrp*8 + ks)*32 + lane)*4];
            #pragma unroll
            for (int nt = 0; nt < 8; ++nt) {
                const uint2 Bh = *(const uint2*)&Bf[((0*64 + nt*8 + ks)*32 + lane)*2];
                const uint2 Bl = *(const uint2*)&Bf[((1*64 + nt*8 + ks)*32 + lane)*2];
                mma16816(acc[nt], Ah, Bh);
                mma16816(acc[nt], Ah, Bl);
                mma16816(acc[nt], Al, Bh);
            }
        }
        #pragma unroll
        for (int nt = 0; nt < 8; ++nt) {
            const int col = nc*64 + nt*8 + 2*(lane&3);
            const float2 bias = *(const float2*)(b_out + col);
            float2 v0; v0.x = acc[nt][0]+bias.x; v0.y = acc[nt][1]+bias.y;
            float2 v1; v1.x = acc[nt][2]+bias.x; v1.y = acc[nt][3]+bias.y;
            *(float2*)(oA + col) = v0;
            *(float2*)(oB + col) = v1;
        }
    }
}

extern "C" void kernel_launch(void* const* d_in, const int* in_sizes, int n_in,
                              void* d_out, int out_size)
{
    const float* x     = (const float*)d_in[0];
    const float* ln_g  = (const float*)d_in[1];
    const float* ln_b  = (const float*)d_in[2];
    const float* w_qkv = (const float*)d_in[3];
    const float* b_qkv = (const float*)d_in[4];
    const float* w_out = (const float*)d_in[5];
    const float* b_out = (const float*)d_in[6];
    float* out = (float*)d_out;

    const int smG = SM_GEMM_BYTES;              // 98304
    const int smA = 3*NHH*NTOK*HDP*4;           // 84672
    cudaFuncSetAttribute(k1_ln_qkv, cudaFuncAttributeMaxDynamicSharedMemorySize, smG);
    cudaFuncSetAttribute(k2_attn,  cudaFuncAttributeMaxDynamicSharedMemorySize, smA);
    cudaFuncSetAttribute(k3_proj,  cudaFuncAttributeMaxDynamicSharedMemorySize, smG);

    k1_ln_qkv<<<1568, 256, smG>>>(x, ln_g, ln_b, w_qkv, b_qkv);
    k2_attn<<<NWIN, 256, smA>>>();
    k3_proj<<<1568, 256, smG>>>(w_out, b_out, out);
}